// round 15
// baseline (speedup 1.0000x reference)
#include <cuda_runtime.h>
#include <cuda_bf16.h>
#include <cuda_fp16.h>
#include <cstdint>
#include <math.h>

#define BB 8
#define TB 256
#define SB 256
#define HH 512

// ---------------------------------------------------------------------------
// Static device scratch
// ---------------------------------------------------------------------------
__device__ __nv_bfloat16 g_in3[2 * 2048 * 1536];  // query|enc 2-term A splits (K'=1024)
__device__ __nv_bfloat16 g_W12[2 * 512 * 1536];   // W_s|W_h 2-term B splits (K'=1024)
__device__ __nv_bfloat16 g_Wo3[512 * 3072];       // W_out 3-term B split [ctx|q] blocks
__device__ __half g_WWh[2 * 2048 * 512];          // WsQ | WhE  (half)
__device__ __nv_bfloat16 g_A5[2048 * 3072];       // [ctx3|q3] split (A-form)
__device__ __nv_bfloat16 g_attnS[BB * TB * 768];  // attn 3-term split (A-form)
__device__ __nv_bfloat16 g_eT[BB * HH * 768];     // enc^T 3-term split (B-form)
__device__ float g_P5[4 * 2048 * 512];            // 4 split-K partials (ctx x2, q x2)

typedef unsigned long long u64;

__device__ __forceinline__ uint32_t smem_u32(const void* p) {
    uint32_t a;
    asm("{ .reg .u64 t; cvta.to.shared.u64 t, %1; cvt.u32.u64 %0, t; }" : "=r"(a) : "l"(p));
    return a;
}
__device__ __forceinline__ void bfsplit(float x, __nv_bfloat16& h, __nv_bfloat16& l) {
    h = __float2bfloat16(x);
    l = __float2bfloat16(x - __bfloat162float(h));
}
__device__ __forceinline__ float2 tanh2h(__half2 x) {
    uint32_t u = *reinterpret_cast<uint32_t*>(&x);
    asm("tanh.approx.f16x2 %0, %0;" : "+r"(u));
    __half2 t = *reinterpret_cast<__half2*>(&u);
    return __half22float2(t);
}

#define CP_ASYNC16(dst, src) \
    asm volatile("cp.async.cg.shared.global [%0], [%1], 16;" :: "r"(dst), "l"(src))
#define CP_COMMIT() asm volatile("cp.async.commit_group;" ::: "memory")
#define CP_WAIT1()  asm volatile("cp.async.wait_group 1;" ::: "memory")
#define CP_WAIT0()  asm volatile("cp.async.wait_group 0;" ::: "memory")

// ---------------------------------------------------------------------------
// Fused conversions
// ---------------------------------------------------------------------------
// query+enc -> 2-term A-form (K'=1024) in g_in3; query -> A5 q-block [1536,3072)
__global__ void __launch_bounds__(256) conv_inputs(
    const float* __restrict__ q, const float* __restrict__ enc)
{
    int t = blockIdx.x * 256 + threadIdx.x;
    const int perT = 2048 * 512 / 4;
    bool isQ = t < perT;
    int i4 = isQ ? t : t - perT;
    int r = i4 >> 7, k = (i4 & 127) << 2;
    const float* src = isQ ? q : enc;
    float4 x = *(const float4*)&src[(size_t)r * 512 + k];
    __nv_bfloat16 h0, l0, h1, l1, h2, l2, h3, l3;
    bfsplit(x.x, h0, l0); bfsplit(x.y, h1, l1);
    bfsplit(x.z, h2, l2); bfsplit(x.w, h3, l3);
    __nv_bfloat162 hA(h0, h1), hB(h2, h3), lA(l0, l1), lB(l2, l3);

    size_t base = (isQ ? 0 : (size_t)2048 * 1024) + (size_t)r * 1024 + k;
    *(__nv_bfloat162*)&g_in3[base]           = hA;
    *(__nv_bfloat162*)&g_in3[base + 2]       = hB;
    *(__nv_bfloat162*)&g_in3[base + 512]     = lA;
    *(__nv_bfloat162*)&g_in3[base + 512 + 2] = lB;

    if (isQ) {
        // q 3-term block at cols [1536,3072): hi, lo(+512), hi(+1024)
        size_t b5 = (size_t)r * 3072 + 1536 + k;
        *(__nv_bfloat162*)&g_A5[b5]            = hA;
        *(__nv_bfloat162*)&g_A5[b5 + 2]        = hB;
        *(__nv_bfloat162*)&g_A5[b5 + 512]      = lA;
        *(__nv_bfloat162*)&g_A5[b5 + 512 + 2]  = lB;
        *(__nv_bfloat162*)&g_A5[b5 + 1024]     = hA;
        *(__nv_bfloat162*)&g_A5[b5 + 1024 + 2] = hB;
    }
}

// W_s/W_h -> 2-term B-form (K'=1024); W_out -> 3-term B-form blocked [ctx|q]
__global__ void __launch_bounds__(256) conv_weights(
    const float* __restrict__ Ws, const float* __restrict__ Wh,
    const float* __restrict__ Wo)
{
    int t = blockIdx.x * 256 + threadIdx.x;
    if (t < 131072) {
        const float* src; __nv_bfloat16* dst; int i4;
        if (t < 65536) { src = Ws; dst = g_W12;              i4 = t; }
        else           { src = Wh; dst = g_W12 + 512 * 1024; i4 = t - 65536; }
        int r = i4 >> 7, k = (i4 & 127) << 2;
        float4 x = *(const float4*)&src[(size_t)r * 512 + k];
        __nv_bfloat162 hA(__float2bfloat16(x.x), __float2bfloat16(x.y));
        __nv_bfloat162 hB(__float2bfloat16(x.z), __float2bfloat16(x.w));
        size_t base = (size_t)r * 1024 + k;
        *(__nv_bfloat162*)&dst[base]           = hA;
        *(__nv_bfloat162*)&dst[base + 2]       = hB;
        *(__nv_bfloat162*)&dst[base + 512]     = hA;
        *(__nv_bfloat162*)&dst[base + 512 + 2] = hB;
    } else {
        int i4 = t - 131072;               // W_out: 512x1024
        int r = i4 >> 8, k = (i4 & 255) << 2;
        float4 x = *(const float4*)&Wo[(size_t)r * 1024 + k];
        __nv_bfloat16 h0, l0, h1, l1, h2, l2, h3, l3;
        bfsplit(x.x, h0, l0); bfsplit(x.y, h1, l1);
        bfsplit(x.z, h2, l2); bfsplit(x.w, h3, l3);
        __nv_bfloat162 hA(h0, h1), hB(h2, h3), lA(l0, l1), lB(l2, l3);
        // ctx cols (k<512) -> [0,1536): hi, hi(+512), lo(+1024)
        // q cols  (k>=512) -> [1536,3072): hi, hi(+512), lo(+1024)
        size_t c0 = (k < 512) ? (size_t)k : (size_t)(1024 + k);
        size_t base = (size_t)r * 3072 + c0;
        *(__nv_bfloat162*)&g_Wo3[base]            = hA;
        *(__nv_bfloat162*)&g_Wo3[base + 2]        = hB;
        *(__nv_bfloat162*)&g_Wo3[base + 512]      = hA;
        *(__nv_bfloat162*)&g_Wo3[base + 512 + 2]  = hB;
        *(__nv_bfloat162*)&g_Wo3[base + 1024]     = lA;
        *(__nv_bfloat162*)&g_Wo3[base + 1024 + 2] = lB;
    }
}

__global__ void __launch_bounds__(256) transpose_split_enc(
    const float* __restrict__ enc, __nv_bfloat16* __restrict__ eT)
{
    __shared__ float tile[32][33];
    const int h0 = blockIdx.x * 32, s0 = blockIdx.y * 32, b = blockIdx.z;
    const int tx = threadIdx.x & 31, ty = threadIdx.x >> 5;
    const float* ep = enc + ((size_t)b * SB + s0) * HH + h0;
#pragma unroll
    for (int i = 0; i < 4; i++)
        tile[ty + 8 * i][tx] = ep[(size_t)(ty + 8 * i) * HH + tx];
    __syncthreads();
#pragma unroll
    for (int i = 0; i < 4; i++) {
        int hl = ty + 8 * i, sl = tx;
        __nv_bfloat16 h, l; bfsplit(tile[sl][hl], h, l);
        size_t base = ((size_t)b * HH + h0 + hl) * 768 + s0 + sl;
        eT[base] = h; eT[base + 256] = h; eT[base + 512] = l;
    }
}

// ---------------------------------------------------------------------------
// HMMA GEMM, 3-stage cp.async ring + register-fragment pipeline.
// EPI: 0 fp32 | 1 tanh fp32 | 2 hi/lo/hi bf16 split (A5 ctx block) | 3 half
// ---------------------------------------------------------------------------
__device__ __forceinline__ void mma16816(float* c, const uint32_t* a, const uint32_t* b) {
    asm volatile(
        "mma.sync.aligned.m16n8k16.row.col.f32.bf16.bf16.f32 "
        "{%0,%1,%2,%3}, {%4,%5,%6,%7}, {%8,%9}, {%0,%1,%2,%3};"
        : "+f"(c[0]), "+f"(c[1]), "+f"(c[2]), "+f"(c[3])
        : "r"(a[0]), "r"(a[1]), "r"(a[2]), "r"(a[3]), "r"(b[0]), "r"(b[1]));
}

template <int EPI, int NT>
__global__ void __launch_bounds__(256) hmma_gemm(
    const __nv_bfloat16* __restrict__ A, const __nv_bfloat16* __restrict__ B,
    void* Cv, int K_len, int Kld, int ldc, size_t strA, size_t strB, size_t strC,
    const int* __restrict__ lens)
{
    constexpr int NPG = NT / 32;
    constexpr int NTT = NT / 16;
    constexpr uint32_t ASZ = 128 * 40 * 2;
    constexpr uint32_t BSZ = NT * 40 * 2;

    __shared__ __align__(16) __nv_bfloat16 As[3][128][40];
    __shared__ __align__(16) __nv_bfloat16 Bs[3][NT][40];

    const int row0 = blockIdx.y * 128, col0 = blockIdx.x * NT;
    if (lens != nullptr && blockIdx.z == 1) {
        if ((row0 & 255) >= lens[row0 >> 8]) return;
    }

    A += (size_t)blockIdx.z * strA;
    B += (size_t)blockIdx.z * strB;

    const int tid = threadIdx.x, wid = tid >> 5, lane = tid & 31;
    const int wm = wid & 3, wn = wid >> 2;

    float acc[2][NTT][4];
#pragma unroll
    for (int mt = 0; mt < 2; mt++)
#pragma unroll
        for (int nt = 0; nt < NTT; nt++)
#pragma unroll
            for (int i = 0; i < 4; i++) acc[mt][nt][i] = 0.f;

    uint32_t a_addr[2], b_addr[NPG];
#pragma unroll
    for (int mt = 0; mt < 2; mt++) {
        int r = wm * 32 + mt * 16 + (lane & 7) + ((lane >> 3) & 1) * 8;
        int k = (lane >> 4) * 8;
        a_addr[mt] = smem_u32(&As[0][r][k]);
    }
#pragma unroll
    for (int np = 0; np < NPG; np++) {
        int n = wn * (NT / 2) + np * 16 + (lane & 7) + (lane >> 4) * 8;
        int k = ((lane >> 3) & 1) * 8;
        b_addr[np] = smem_u32(&Bs[0][n][k]);
    }

    const int arow = tid >> 2, acol = (tid & 3) * 8;
    uint32_t sA0 = smem_u32(&As[0][arow][acol]);
    uint32_t sA1 = smem_u32(&As[0][64 + arow][acol]);
    uint32_t sB0 = smem_u32(&Bs[0][arow][acol]);
    uint32_t sB1 = (NT == 128) ? smem_u32(&Bs[0][(NT == 128 ? 64 : 0) + arow][acol]) : 0;
    const __nv_bfloat16* gA0 = A + (size_t)(row0 + arow) * Kld + acol;
    const __nv_bfloat16* gA1 = A + (size_t)(row0 + 64 + arow) * Kld + acol;
    const __nv_bfloat16* gB0 = B + (size_t)(col0 + arow) * Kld + acol;
    const __nv_bfloat16* gB1 = (NT == 128)
        ? B + (size_t)(col0 + 64 + arow) * Kld + acol : gB0;

#define ISSUE(kc, st) do { \
    uint32_t ao = (uint32_t)(st) * ASZ, bo = (uint32_t)(st) * BSZ; \
    CP_ASYNC16(sA0 + ao, gA0 + (kc)); \
    CP_ASYNC16(sA1 + ao, gA1 + (kc)); \
    CP_ASYNC16(sB0 + bo, gB0 + (kc)); \
    if (NT == 128) CP_ASYNC16(sB1 + bo, gB1 + (kc)); \
    CP_COMMIT(); \
} while (0)

    uint32_t afr[2][2][4];
    uint32_t bfr[2][NTT][2];

#define LDFRAG(buf, ao, bo, ks) do { \
    _Pragma("unroll") \
    for (int mt = 0; mt < 2; mt++) { \
        asm volatile("ldmatrix.sync.aligned.m8n8.x4.shared.b16 {%0,%1,%2,%3}, [%4];" \
            : "=r"(afr[buf][mt][0]), "=r"(afr[buf][mt][1]), \
              "=r"(afr[buf][mt][2]), "=r"(afr[buf][mt][3]) \
            : "r"(a_addr[mt] + (ao) + (ks) * 32)); \
    } \
    _Pragma("unroll") \
    for (int np = 0; np < NPG; np++) { \
        asm volatile("ldmatrix.sync.aligned.m8n8.x4.shared.b16 {%0,%1,%2,%3}, [%4];" \
            : "=r"(bfr[buf][np * 2][0]),     "=r"(bfr[buf][np * 2][1]), \
              "=r"(bfr[buf][np * 2 + 1][0]), "=r"(bfr[buf][np * 2 + 1][1]) \
            : "r"(b_addr[np] + (bo) + (ks) * 32)); \
    } \
} while (0)

#define MMAALL(buf) do { \
    _Pragma("unroll") \
    for (int mt = 0; mt < 2; mt++) \
        _Pragma("unroll") \
        for (int nt = 0; nt < NTT; nt++) \
            mma16816(acc[mt][nt], afr[buf][mt], bfr[buf][nt]); \
} while (0)

    const int nch = K_len >> 5;
    ISSUE(0, 0);
    if (nch > 1) ISSUE(32, 1);
    CP_WAIT0();
    __syncthreads();
    if (nch > 2) ISSUE(64, 2);

    LDFRAG(0, 0u, 0u, 0);

    int stage = 0;
    for (int i = 0; i < nch; i++) {
        const uint32_t aoff = (uint32_t)stage * ASZ, boff = (uint32_t)stage * BSZ;
        int ns = stage + 1; if (ns == 3) ns = 0;
        const uint32_t naoff = (uint32_t)ns * ASZ, nboff = (uint32_t)ns * BSZ;

        LDFRAG(1, aoff, boff, 1);
        MMAALL(0);
        if (i + 1 < nch) LDFRAG(0, naoff, nboff, 0);
        MMAALL(1);

        if (i + 1 < nch) {
            CP_WAIT0();
            __syncthreads();
            if (i + 3 < nch) ISSUE((i + 3) << 5, stage);
        }
        stage = ns;
    }
#undef ISSUE
#undef LDFRAG
#undef MMAALL

    if (EPI == 2) {
        // ctx 3-term block store at A5 cols [0,1536): hi, lo(+512), hi(+1024)
        __nv_bfloat16* Cb = (__nv_bfloat16*)Cv + (size_t)blockIdx.z * strC;
#pragma unroll
        for (int mt = 0; mt < 2; mt++)
#pragma unroll
            for (int nt = 0; nt < NTT; nt++) {
                int m = row0 + wm * 32 + mt * 16 + (lane >> 2);
                int n = col0 + wn * (NT / 2) + nt * 8 + 2 * (lane & 3);
#pragma unroll
                for (int rr = 0; rr < 2; rr++) {
                    int mr = m + rr * 8;
                    float v0 = acc[mt][nt][rr * 2], v1 = acc[mt][nt][rr * 2 + 1];
                    __nv_bfloat16 h0, l0, h1, l1;
                    bfsplit(v0, h0, l0); bfsplit(v1, h1, l1);
                    size_t base = (size_t)mr * ldc + n;
                    *(__nv_bfloat162*)&Cb[base]        = __nv_bfloat162(h0, h1);
                    *(__nv_bfloat162*)&Cb[base + 512]  = __nv_bfloat162(l0, l1);
                    *(__nv_bfloat162*)&Cb[base + 1024] = __nv_bfloat162(h0, h1);
                }
            }
    } else if (EPI == 3) {
        __half* Ch = (__half*)Cv + (size_t)blockIdx.z * strC;
#pragma unroll
        for (int mt = 0; mt < 2; mt++)
#pragma unroll
            for (int nt = 0; nt < NTT; nt++) {
                int m = row0 + wm * 32 + mt * 16 + (lane >> 2);
                int n = col0 + wn * (NT / 2) + nt * 8 + 2 * (lane & 3);
                *(__half2*)&Ch[(size_t)m * ldc + n] =
                    __floats2half2_rn(acc[mt][nt][0], acc[mt][nt][1]);
                *(__half2*)&Ch[(size_t)(m + 8) * ldc + n] =
                    __floats2half2_rn(acc[mt][nt][2], acc[mt][nt][3]);
            }
    } else {
        float* Cf = (float*)Cv + (size_t)blockIdx.z * strC;
#pragma unroll
        for (int mt = 0; mt < 2; mt++)
#pragma unroll
            for (int nt = 0; nt < NTT; nt++) {
                int m = row0 + wm * 32 + mt * 16 + (lane >> 2);
                int n = col0 + wn * (NT / 2) + nt * 8 + 2 * (lane & 3);
                float c0 = acc[mt][nt][0], c1 = acc[mt][nt][1];
                float c2 = acc[mt][nt][2], c3 = acc[mt][nt][3];
                if (EPI == 1) { c0 = tanhf(c0); c1 = tanhf(c1); c2 = tanhf(c2); c3 = tanhf(c3); }
                *(float2*)&Cf[(size_t)m * ldc + n] = make_float2(c0, c1);
                *(float2*)&Cf[(size_t)(m + 8) * ldc + n] = make_float2(c2, c3);
            }
    }
}

// 4-way split-K reduction + tanh
__global__ void __launch_bounds__(256) reduce4_tanh(
    const float* __restrict__ P, float* __restrict__ out)
{
    const size_t N = (size_t)2048 * 512;
    int i4 = blockIdx.x * 256 + threadIdx.x;
    float4 a = *(const float4*)&P[(size_t)i4 * 4];
    float4 b = *(const float4*)&P[N + (size_t)i4 * 4];
    float4 c = *(const float4*)&P[2 * N + (size_t)i4 * 4];
    float4 d = *(const float4*)&P[3 * N + (size_t)i4 * 4];
    float4 o = make_float4(tanhf((a.x + b.x) + (c.x + d.x)),
                           tanhf((a.y + b.y) + (c.y + d.y)),
                           tanhf((a.z + b.z) + (c.z + d.z)),
                           tanhf((a.w + b.w) + (c.w + d.w)));
    *(float4*)&out[(size_t)i4 * 4] = o;
}

// ---------------------------------------------------------------------------
// Energies + masked softmax (v6: ring, staging skip, ngrp skip, f16x2 tanh)
// ---------------------------------------------------------------------------
#define EN_G(bp, accv) do { \
    float2 t = tanh2h(__hadd2(a2, (bp)[hp])); \
    accv = fmaf(v2.x, t.x, fmaf(v2.y, t.y, accv)); \
} while (0)

#define EN_HPLOOP(NG) \
    _Pragma("unroll") \
    for (int hp = 0; hp < 8; hp++) { \
        __half2 a2 = ar[hp]; \
        float2 v2 = *(const float2*)&vr[hp << 1]; \
        EN_G(b0, acc0); \
        if ((NG) > 1) EN_G(b1, acc1); \
        if ((NG) > 2) EN_G(b2, acc2); \
        if ((NG) > 3) EN_G(b3, acc3); \
    }

__global__ void __launch_bounds__(256) attn_energy_softmax(
    const int* __restrict__ lens, const float* __restrict__ v)
{
    __shared__ __align__(16) __half sBst[3][256 * 24];
    __shared__ __align__(16) __half sAh[4 * 520];
    __shared__ __align__(16) float sV[HH];
    __shared__ __align__(16) float eS[4 * 260];
    __shared__ float red[8];

    const int b  = blockIdx.y;
    const int t0 = blockIdx.x << 2;
    const int tid = threadIdx.x;
    const int t_local = tid & 3, sg = tid >> 2;
    const __half* WsQh = g_WWh;
    const __half* WhEh = g_WWh + (size_t)2048 * 512;
    const int len = lens[b];

    const int ngrp = (sg < len) ? min(4, ((len - 1 - sg) >> 6) + 1) : 0;

    {
        int row = tid >> 6, col = (tid & 63) << 3;
        uint4 x = *(const uint4*)&WsQh[((size_t)(b * TB + t0 + row)) * HH + col];
        *(uint4*)&sAh[row * 520 + col] = x;
    }
    for (int i = tid; i < HH; i += 256) sV[i] = v[i];

    const int srow0 = tid >> 1, sq = tid & 1;
    const bool st0 = srow0 < len;
    const bool st1 = srow0 + 128 < len;
    uint32_t dst0 = smem_u32(&sBst[0][srow0 * 24 + sq * 8]);
    uint32_t dst1 = smem_u32(&sBst[0][(srow0 + 128) * 24 + sq * 8]);
    const __half* src0 = WhEh + ((size_t)(b * SB) + srow0) * HH + sq * 8;
    const __half* src1 = WhEh + ((size_t)(b * SB) + srow0 + 128) * HH + sq * 8;
    const uint32_t BUFSZ = 256 * 24 * 2;

#define STAGE(hc, buf) do { \
    uint32_t o = (uint32_t)(buf) * BUFSZ; \
    if (st0) CP_ASYNC16(dst0 + o, src0 + ((hc) << 4)); \
    if (st1) CP_ASYNC16(dst1 + o, src1 + ((hc) << 4)); \
    CP_COMMIT(); \
} while (0)

    float acc0 = 0.f, acc1 = 0.f, acc2 = 0.f, acc3 = 0.f;

    STAGE(0, 0);
    STAGE(1, 1);

    int bufc = 0, bufn = 2;
    for (int hc = 0; hc < 32; hc++) {
        if (hc < 31) { CP_WAIT1(); } else { CP_WAIT0(); }
        __syncthreads();
        if (hc + 2 < 32) STAGE(hc + 2, bufn);

        const __half2* ar = (const __half2*)&sAh[t_local * 520 + (hc << 4)];
        const float*   vr = &sV[hc << 4];
        const __half2* b0 = (const __half2*)&sBst[bufc][sg * 24];
        const __half2* b1 = b0 + 64 * 12;
        const __half2* b2 = b0 + 128 * 12;
        const __half2* b3 = b0 + 192 * 12;

        switch (ngrp) {
            case 4: EN_HPLOOP(4); break;
            case 3: EN_HPLOOP(3); break;
            case 2: EN_HPLOOP(2); break;
            case 1: EN_HPLOOP(1); break;
            default: break;
        }

        bufc = (bufc + 1 == 3) ? 0 : bufc + 1;
        bufn = (bufn + 1 == 3) ? 0 : bufn + 1;
    }
#undef STAGE

    __syncthreads();
    eS[t_local * 260 + sg +   0] = acc0;
    eS[t_local * 260 + sg +  64] = acc1;
    eS[t_local * 260 + sg + 128] = acc2;
    eS[t_local * 260 + sg + 192] = acc3;
    __syncthreads();

    const int r = tid >> 6, k = tid & 63, s0 = k << 2;
    float4 ev = *(float4*)(eS + r * 260 + s0);

    float mloc = -3.0e38f;
    if (s0 + 0 < len) mloc = fmaxf(mloc, ev.x);
    if (s0 + 1 < len) mloc = fmaxf(mloc, ev.y);
    if (s0 + 2 < len) mloc = fmaxf(mloc, ev.z);
    if (s0 + 3 < len) mloc = fmaxf(mloc, ev.w);
#pragma unroll
    for (int o = 16; o; o >>= 1) mloc = fmaxf(mloc, __shfl_xor_sync(~0u, mloc, o));
    if ((tid & 31) == 0) red[tid >> 5] = mloc;
    __syncthreads();
    float m = fmaxf(red[2 * r], red[2 * r + 1]);

    float e0 = (s0 + 0 < len) ? __expf(ev.x - m) : 0.f;
    float e1 = (s0 + 1 < len) ? __expf(ev.y - m) : 0.f;
    float e2 = (s0 + 2 < len) ? __expf(ev.z - m) : 0.f;
    float e3 = (s0 + 3 < len) ? __expf(ev.w - m) : 0.f;
    float sloc = e0 + e1 + e2 + e3;
#pragma unroll
    for (int o = 16; o; o >>= 1) sloc += __shfl_xor_sync(~0u, sloc, o);
    __syncthreads();
    if ((tid & 31) == 0) red[tid >> 5] = sloc;
    __syncthreads();
    float inv = 1.f / (red[2 * r] + red[2 * r + 1]);

    float w0 = e0 * inv, w1 = e1 * inv, w2 = e2 * inv, w3 = e3 * inv;
    __nv_bfloat16 h0, l0, h1, l1, h2, l2, h3, l3;
    bfsplit(w0, h0, l0); bfsplit(w1, h1, l1);
    bfsplit(w2, h2, l2); bfsplit(w3, h3, l3);
    size_t rb = ((size_t)(b * TB + t0 + r)) * 768;
    __nv_bfloat162 hA(h0, h1), hB(h2, h3), lA(l0, l1), lB(l2, l3);
    *(__nv_bfloat162*)&g_attnS[rb + s0]           = hA;
    *(__nv_bfloat162*)&g_attnS[rb + s0 + 2]       = hB;
    *(__nv_bfloat162*)&g_attnS[rb + 256 + s0]     = lA;
    *(__nv_bfloat162*)&g_attnS[rb + 256 + s0 + 2] = lB;
    *(__nv_bfloat162*)&g_attnS[rb + 512 + s0]     = hA;
    *(__nv_bfloat162*)&g_attnS[rb + 512 + s0 + 2] = hB;
}

// ---------------------------------------------------------------------------

extern "C" void kernel_launch(void* const* d_in, const int* in_sizes, int n_in,
                              void* d_out, int out_size)
{
    (void)in_sizes; (void)n_in; (void)out_size;
    const float* query = (const float*)d_in[0];
    const float* enc   = (const float*)d_in[1];
    const int*   lens  = (const int*)d_in[2];
    const float* W_s   = (const float*)d_in[3];
    const float* W_h   = (const float*)d_in[4];
    const float* v     = (const float*)d_in[5];
    const float* W_out = (const float*)d_in[6];
    float* out = (float*)d_out;

    __nv_bfloat16 *pin3, *pW12, *pWo3, *pA5, *pAttnS, *peT;
    __half* pWWh;
    float* pP5;
    cudaGetSymbolAddress((void**)&pin3, g_in3);
    cudaGetSymbolAddress((void**)&pW12, g_W12);
    cudaGetSymbolAddress((void**)&pWo3, g_Wo3);
    cudaGetSymbolAddress((void**)&pWWh, g_WWh);
    cudaGetSymbolAddress((void**)&pA5, g_A5);
    cudaGetSymbolAddress((void**)&pAttnS, g_attnS);
    cudaGetSymbolAddress((void**)&peT, g_eT);
    cudaGetSymbolAddress((void**)&pP5, g_P5);
    float* pP5q = pP5 + (size_t)2 * 2048 * 512;

    // Fork a side stream inside capture (event fork/join pattern).
    cudaStream_t s1;
    cudaStreamCreateWithFlags(&s1, cudaStreamNonBlocking);
    cudaEvent_t evF, evCI, evCW, evQ;
    cudaEventCreateWithFlags(&evF,  cudaEventDisableTiming);
    cudaEventCreateWithFlags(&evCI, cudaEventDisableTiming);
    cudaEventCreateWithFlags(&evCW, cudaEventDisableTiming);
    cudaEventCreateWithFlags(&evQ,  cudaEventDisableTiming);

    cudaEventRecord(evF, 0);
    cudaStreamWaitEvent(s1, evF, 0);

    // s0: input conversions
    conv_inputs<<<2048, 256>>>(query, enc);
    cudaEventRecord(evCI, 0);

    // s1: weight conversions + transpose, then q-half of output GEMM
    conv_weights<<<1024, 256, 0, s1>>>(W_s, W_h, W_out);
    transpose_split_enc<<<dim3(16, 8, 8), 256, 0, s1>>>(enc, peT);
    cudaEventRecord(evCW, s1);
    cudaStreamWaitEvent(s1, evCI, 0);
    // GEMM5q: q@Wq^T (3-term, K segment [1536,3072), split-K x2) -> P5q
    hmma_gemm<0, 128><<<dim3(4, 16, 2), 256, 0, s1>>>(
        pA5 + 1536, pWo3 + 1536, pP5q, 768, 3072, 512,
        (size_t)768, (size_t)768, (size_t)2048 * 512, nullptr);
    cudaEventRecord(evQ, s1);

    // s0: main chain (needs W12 + eT)
    cudaStreamWaitEvent(0, evCW, 0);
    hmma_gemm<3, 128><<<dim3(4, 16, 2), 256>>>(pin3, pW12, pWWh, 1024, 1024, 512,
                                               (size_t)2048 * 1024, (size_t)512 * 1024,
                                               (size_t)2048 * 512, lens);
    attn_energy_softmax<<<dim3(64, 8), 256>>>(lens, v);
    // ctx = attn @ enc -> A5 ctx block (3-term store)
    hmma_gemm<2, 64><<<dim3(8, 2, 8), 256>>>(pAttnS, peT, pA5, 768, 768, 3072,
                                             (size_t)TB * 768, (size_t)HH * 768,
                                             (size_t)TB * 3072, nullptr);
    // GEMM5c: ctx@Wc^T (3-term, K segment [0,1536), split-K x2) -> P5[0..1]
    hmma_gemm<0, 128><<<dim3(4, 16, 2), 256>>>(
        pA5, pWo3, pP5, 768, 3072, 512,
        (size_t)768, (size_t)768, (size_t)2048 * 512, nullptr);
    cudaStreamWaitEvent(0, evQ, 0);
    reduce4_tanh<<<1024, 256>>>(pP5, out);

    cudaEventDestroy(evF);
    cudaEventDestroy(evCI);
    cudaEventDestroy(evCW);
    cudaEventDestroy(evQ);
    cudaStreamDestroy(s1);
}

// round 16
// speedup vs baseline: 1.0768x; 1.0768x over previous
#include <cuda_runtime.h>
#include <cuda_bf16.h>
#include <cuda_fp16.h>
#include <cstdint>
#include <math.h>

#define BB 8
#define TB 256
#define SB 256
#define HH 512

// ---------------------------------------------------------------------------
// Static device scratch
// ---------------------------------------------------------------------------
__device__ __nv_bfloat16 g_in3[2 * 2048 * 1536];  // query|enc 2-term A splits (K'=1024)
__device__ __nv_bfloat16 g_W12[2 * 512 * 1536];   // W_s|W_h 2-term B splits (K'=1024)
__device__ __nv_bfloat16 g_Wo3[512 * 3072];       // W_out 3-term B split
__device__ __half g_WWh[2 * 2048 * 512];          // WsQ | WhE  (half)
__device__ __nv_bfloat16 g_A5[2048 * 3072];       // [ctx|query] 3-term split (A-form)
__device__ __nv_bfloat16 g_attnS[BB * TB * 768];  // attn 3-term split (A-form)
__device__ __nv_bfloat16 g_eT[BB * HH * 768];     // enc^T 3-term split (B-form)
__device__ float g_P5[4 * 2048 * 512];            // split-K x4 partials for out GEMM

typedef unsigned long long u64;

__device__ __forceinline__ uint32_t smem_u32(const void* p) {
    uint32_t a;
    asm("{ .reg .u64 t; cvta.to.shared.u64 t, %1; cvt.u32.u64 %0, t; }" : "=r"(a) : "l"(p));
    return a;
}
__device__ __forceinline__ void bfsplit(float x, __nv_bfloat16& h, __nv_bfloat16& l) {
    h = __float2bfloat16(x);
    l = __float2bfloat16(x - __bfloat162float(h));
}
__device__ __forceinline__ float2 tanh2h(__half2 x) {
    uint32_t u = *reinterpret_cast<uint32_t*>(&x);
    asm("tanh.approx.f16x2 %0, %0;" : "+r"(u));
    __half2 t = *reinterpret_cast<__half2*>(&u);
    return __half22float2(t);
}

#define CP_ASYNC16(dst, src) \
    asm volatile("cp.async.cg.shared.global [%0], [%1], 16;" :: "r"(dst), "l"(src))
#define CP_COMMIT() asm volatile("cp.async.commit_group;" ::: "memory")
#define CP_WAIT1()  asm volatile("cp.async.wait_group 1;" ::: "memory")
#define CP_WAIT0()  asm volatile("cp.async.wait_group 0;" ::: "memory")

// ---------------------------------------------------------------------------
// Fused conversions (R14 layouts)
// ---------------------------------------------------------------------------
__global__ void __launch_bounds__(256) conv_inputs(
    const float* __restrict__ q, const float* __restrict__ enc)
{
    int t = blockIdx.x * 256 + threadIdx.x;
    const int perT = 2048 * 512 / 4;
    bool isQ = t < perT;
    int i4 = isQ ? t : t - perT;
    int r = i4 >> 7, k = (i4 & 127) << 2;
    const float* src = isQ ? q : enc;
    float4 x = *(const float4*)&src[(size_t)r * 512 + k];
    __nv_bfloat16 h0, l0, h1, l1, h2, l2, h3, l3;
    bfsplit(x.x, h0, l0); bfsplit(x.y, h1, l1);
    bfsplit(x.z, h2, l2); bfsplit(x.w, h3, l3);
    __nv_bfloat162 hA(h0, h1), hB(h2, h3), lA(l0, l1), lB(l2, l3);

    size_t base = (isQ ? 0 : (size_t)2048 * 1024) + (size_t)r * 1024 + k;
    *(__nv_bfloat162*)&g_in3[base]           = hA;
    *(__nv_bfloat162*)&g_in3[base + 2]       = hB;
    *(__nv_bfloat162*)&g_in3[base + 512]     = lA;
    *(__nv_bfloat162*)&g_in3[base + 512 + 2] = lB;

    if (isQ) {
        size_t b5 = (size_t)r * 3072 + 512 + k;
        *(__nv_bfloat162*)&g_A5[b5]            = hA;
        *(__nv_bfloat162*)&g_A5[b5 + 2]        = hB;
        *(__nv_bfloat162*)&g_A5[b5 + 1024]     = lA;
        *(__nv_bfloat162*)&g_A5[b5 + 1024 + 2] = lB;
        *(__nv_bfloat162*)&g_A5[b5 + 2048]     = hA;
        *(__nv_bfloat162*)&g_A5[b5 + 2048 + 2] = hB;
    }
}

__global__ void __launch_bounds__(256) conv_weights(
    const float* __restrict__ Ws, const float* __restrict__ Wh,
    const float* __restrict__ Wo)
{
    int t = blockIdx.x * 256 + threadIdx.x;
    if (t < 131072) {
        const float* src; __nv_bfloat16* dst; int i4;
        if (t < 65536) { src = Ws; dst = g_W12;              i4 = t; }
        else           { src = Wh; dst = g_W12 + 512 * 1024; i4 = t - 65536; }
        int r = i4 >> 7, k = (i4 & 127) << 2;
        float4 x = *(const float4*)&src[(size_t)r * 512 + k];
        __nv_bfloat162 hA(__float2bfloat16(x.x), __float2bfloat16(x.y));
        __nv_bfloat162 hB(__float2bfloat16(x.z), __float2bfloat16(x.w));
        size_t base = (size_t)r * 1024 + k;
        *(__nv_bfloat162*)&dst[base]           = hA;
        *(__nv_bfloat162*)&dst[base + 2]       = hB;
        *(__nv_bfloat162*)&dst[base + 512]     = hA;
        *(__nv_bfloat162*)&dst[base + 512 + 2] = hB;
    } else {
        int i4 = t - 131072;
        int r = i4 >> 8, k = (i4 & 255) << 2;
        float4 x = *(const float4*)&Wo[(size_t)r * 1024 + k];
        __nv_bfloat16 h0, l0, h1, l1, h2, l2, h3, l3;
        bfsplit(x.x, h0, l0); bfsplit(x.y, h1, l1);
        bfsplit(x.z, h2, l2); bfsplit(x.w, h3, l3);
        __nv_bfloat162 hA(h0, h1), hB(h2, h3), lA(l0, l1), lB(l2, l3);
        size_t base = (size_t)r * 3072 + k;
        *(__nv_bfloat162*)&g_Wo3[base]            = hA;
        *(__nv_bfloat162*)&g_Wo3[base + 2]        = hB;
        *(__nv_bfloat162*)&g_Wo3[base + 1024]     = hA;
        *(__nv_bfloat162*)&g_Wo3[base + 1024 + 2] = hB;
        *(__nv_bfloat162*)&g_Wo3[base + 2048]     = lA;
        *(__nv_bfloat162*)&g_Wo3[base + 2048 + 2] = lB;
    }
}

__global__ void __launch_bounds__(256) transpose_split_enc(
    const float* __restrict__ enc, __nv_bfloat16* __restrict__ eT)
{
    __shared__ float tile[32][33];
    const int h0 = blockIdx.x * 32, s0 = blockIdx.y * 32, b = blockIdx.z;
    const int tx = threadIdx.x & 31, ty = threadIdx.x >> 5;
    const float* ep = enc + ((size_t)b * SB + s0) * HH + h0;
#pragma unroll
    for (int i = 0; i < 4; i++)
        tile[ty + 8 * i][tx] = ep[(size_t)(ty + 8 * i) * HH + tx];
    __syncthreads();
#pragma unroll
    for (int i = 0; i < 4; i++) {
        int hl = ty + 8 * i, sl = tx;
        __nv_bfloat16 h, l; bfsplit(tile[sl][hl], h, l);
        size_t base = ((size_t)b * HH + h0 + hl) * 768 + s0 + sl;
        eT[base] = h; eT[base + 256] = h; eT[base + 512] = l;
    }
}

// ---------------------------------------------------------------------------
// HMMA GEMM, 3-stage cp.async ring + register-fragment pipeline.
// EPI: 0 fp32 | 1 tanh fp32 | 2 hi/lo/hi bf16 split (A5) | 3 half store
// ---------------------------------------------------------------------------
__device__ __forceinline__ void mma16816(float* c, const uint32_t* a, const uint32_t* b) {
    asm volatile(
        "mma.sync.aligned.m16n8k16.row.col.f32.bf16.bf16.f32 "
        "{%0,%1,%2,%3}, {%4,%5,%6,%7}, {%8,%9}, {%0,%1,%2,%3};"
        : "+f"(c[0]), "+f"(c[1]), "+f"(c[2]), "+f"(c[3])
        : "r"(a[0]), "r"(a[1]), "r"(a[2]), "r"(a[3]), "r"(b[0]), "r"(b[1]));
}

template <int EPI, int NT>
__global__ void __launch_bounds__(256) hmma_gemm(
    const __nv_bfloat16* __restrict__ A, const __nv_bfloat16* __restrict__ B,
    void* Cv, int K_len, int Kld, int ldc, size_t strA, size_t strB, size_t strC,
    const int* __restrict__ lens)
{
    constexpr int NPG = NT / 32;
    constexpr int NTT = NT / 16;
    constexpr uint32_t ASZ = 128 * 40 * 2;
    constexpr uint32_t BSZ = NT * 40 * 2;

    __shared__ __align__(16) __nv_bfloat16 As[3][128][40];
    __shared__ __align__(16) __nv_bfloat16 Bs[3][NT][40];

    const int row0 = blockIdx.y * 128, col0 = blockIdx.x * NT;
    if (lens != nullptr && blockIdx.z == 1) {
        if ((row0 & 255) >= lens[row0 >> 8]) return;
    }

    A += (size_t)blockIdx.z * strA;
    B += (size_t)blockIdx.z * strB;

    const int tid = threadIdx.x, wid = tid >> 5, lane = tid & 31;
    const int wm = wid & 3, wn = wid >> 2;

    float acc[2][NTT][4];
#pragma unroll
    for (int mt = 0; mt < 2; mt++)
#pragma unroll
        for (int nt = 0; nt < NTT; nt++)
#pragma unroll
            for (int i = 0; i < 4; i++) acc[mt][nt][i] = 0.f;

    uint32_t a_addr[2], b_addr[NPG];
#pragma unroll
    for (int mt = 0; mt < 2; mt++) {
        int r = wm * 32 + mt * 16 + (lane & 7) + ((lane >> 3) & 1) * 8;
        int k = (lane >> 4) * 8;
        a_addr[mt] = smem_u32(&As[0][r][k]);
    }
#pragma unroll
    for (int np = 0; np < NPG; np++) {
        int n = wn * (NT / 2) + np * 16 + (lane & 7) + (lane >> 4) * 8;
        int k = ((lane >> 3) & 1) * 8;
        b_addr[np] = smem_u32(&Bs[0][n][k]);
    }

    const int arow = tid >> 2, acol = (tid & 3) * 8;
    uint32_t sA0 = smem_u32(&As[0][arow][acol]);
    uint32_t sA1 = smem_u32(&As[0][64 + arow][acol]);
    uint32_t sB0 = smem_u32(&Bs[0][arow][acol]);
    uint32_t sB1 = (NT == 128) ? smem_u32(&Bs[0][(NT == 128 ? 64 : 0) + arow][acol]) : 0;
    const __nv_bfloat16* gA0 = A + (size_t)(row0 + arow) * Kld + acol;
    const __nv_bfloat16* gA1 = A + (size_t)(row0 + 64 + arow) * Kld + acol;
    const __nv_bfloat16* gB0 = B + (size_t)(col0 + arow) * Kld + acol;
    const __nv_bfloat16* gB1 = (NT == 128)
        ? B + (size_t)(col0 + 64 + arow) * Kld + acol : gB0;

#define ISSUE(kc, st) do { \
    uint32_t ao = (uint32_t)(st) * ASZ, bo = (uint32_t)(st) * BSZ; \
    CP_ASYNC16(sA0 + ao, gA0 + (kc)); \
    CP_ASYNC16(sA1 + ao, gA1 + (kc)); \
    CP_ASYNC16(sB0 + bo, gB0 + (kc)); \
    if (NT == 128) CP_ASYNC16(sB1 + bo, gB1 + (kc)); \
    CP_COMMIT(); \
} while (0)

    uint32_t afr[2][2][4];
    uint32_t bfr[2][NTT][2];

#define LDFRAG(buf, ao, bo, ks) do { \
    _Pragma("unroll") \
    for (int mt = 0; mt < 2; mt++) { \
        asm volatile("ldmatrix.sync.aligned.m8n8.x4.shared.b16 {%0,%1,%2,%3}, [%4];" \
            : "=r"(afr[buf][mt][0]), "=r"(afr[buf][mt][1]), \
              "=r"(afr[buf][mt][2]), "=r"(afr[buf][mt][3]) \
            : "r"(a_addr[mt] + (ao) + (ks) * 32)); \
    } \
    _Pragma("unroll") \
    for (int np = 0; np < NPG; np++) { \
        asm volatile("ldmatrix.sync.aligned.m8n8.x4.shared.b16 {%0,%1,%2,%3}, [%4];" \
            : "=r"(bfr[buf][np * 2][0]),     "=r"(bfr[buf][np * 2][1]), \
              "=r"(bfr[buf][np * 2 + 1][0]), "=r"(bfr[buf][np * 2 + 1][1]) \
            : "r"(b_addr[np] + (bo) + (ks) * 32)); \
    } \
} while (0)

#define MMAALL(buf) do { \
    _Pragma("unroll") \
    for (int mt = 0; mt < 2; mt++) \
        _Pragma("unroll") \
        for (int nt = 0; nt < NTT; nt++) \
            mma16816(acc[mt][nt], afr[buf][mt], bfr[buf][nt]); \
} while (0)

    const int nch = K_len >> 5;
    ISSUE(0, 0);
    if (nch > 1) ISSUE(32, 1);
    CP_WAIT0();
    __syncthreads();
    if (nch > 2) ISSUE(64, 2);

    LDFRAG(0, 0u, 0u, 0);

    int stage = 0;
    for (int i = 0; i < nch; i++) {
        const uint32_t aoff = (uint32_t)stage * ASZ, boff = (uint32_t)stage * BSZ;
        int ns = stage + 1; if (ns == 3) ns = 0;
        const uint32_t naoff = (uint32_t)ns * ASZ, nboff = (uint32_t)ns * BSZ;

        LDFRAG(1, aoff, boff, 1);
        MMAALL(0);
        if (i + 1 < nch) LDFRAG(0, naoff, nboff, 0);
        MMAALL(1);

        if (i + 1 < nch) {
            CP_WAIT0();
            __syncthreads();
            if (i + 3 < nch) ISSUE((i + 3) << 5, stage);
        }
        stage = ns;
    }
#undef ISSUE
#undef LDFRAG
#undef MMAALL

    if (EPI == 2) {
        __nv_bfloat16* Cb = (__nv_bfloat16*)Cv + (size_t)blockIdx.z * strC;
#pragma unroll
        for (int mt = 0; mt < 2; mt++)
#pragma unroll
            for (int nt = 0; nt < NTT; nt++) {
                int m = row0 + wm * 32 + mt * 16 + (lane >> 2);
                int n = col0 + wn * (NT / 2) + nt * 8 + 2 * (lane & 3);
#pragma unroll
                for (int rr = 0; rr < 2; rr++) {
                    int mr = m + rr * 8;
                    float v0 = acc[mt][nt][rr * 2], v1 = acc[mt][nt][rr * 2 + 1];
                    __nv_bfloat16 h0, l0, h1, l1;
                    bfsplit(v0, h0, l0); bfsplit(v1, h1, l1);
                    size_t base = (size_t)mr * ldc + n;
                    *(__nv_bfloat162*)&Cb[base]        = __nv_bfloat162(h0, h1);
                    *(__nv_bfloat162*)&Cb[base + 1024] = __nv_bfloat162(l0, l1);
                    *(__nv_bfloat162*)&Cb[base + 2048] = __nv_bfloat162(h0, h1);
                }
            }
    } else if (EPI == 3) {
        __half* Ch = (__half*)Cv + (size_t)blockIdx.z * strC;
#pragma unroll
        for (int mt = 0; mt < 2; mt++)
#pragma unroll
            for (int nt = 0; nt < NTT; nt++) {
                int m = row0 + wm * 32 + mt * 16 + (lane >> 2);
                int n = col0 + wn * (NT / 2) + nt * 8 + 2 * (lane & 3);
                *(__half2*)&Ch[(size_t)m * ldc + n] =
                    __floats2half2_rn(acc[mt][nt][0], acc[mt][nt][1]);
                *(__half2*)&Ch[(size_t)(m + 8) * ldc + n] =
                    __floats2half2_rn(acc[mt][nt][2], acc[mt][nt][3]);
            }
    } else {
        float* Cf = (float*)Cv + (size_t)blockIdx.z * strC;
#pragma unroll
        for (int mt = 0; mt < 2; mt++)
#pragma unroll
            for (int nt = 0; nt < NTT; nt++) {
                int m = row0 + wm * 32 + mt * 16 + (lane >> 2);
                int n = col0 + wn * (NT / 2) + nt * 8 + 2 * (lane & 3);
                float c0 = acc[mt][nt][0], c1 = acc[mt][nt][1];
                float c2 = acc[mt][nt][2], c3 = acc[mt][nt][3];
                if (EPI == 1) { c0 = tanhf(c0); c1 = tanhf(c1); c2 = tanhf(c2); c3 = tanhf(c3); }
                *(float2*)&Cf[(size_t)m * ldc + n] = make_float2(c0, c1);
                *(float2*)&Cf[(size_t)(m + 8) * ldc + n] = make_float2(c2, c3);
            }
    }
}

// 4-way split-K reduction + tanh
__global__ void __launch_bounds__(256) reduce4_tanh(
    const float* __restrict__ P, float* __restrict__ out)
{
    const size_t N = (size_t)2048 * 512;
    int i4 = blockIdx.x * 256 + threadIdx.x;
    float4 a = *(const float4*)&P[(size_t)i4 * 4];
    float4 b = *(const float4*)&P[N + (size_t)i4 * 4];
    float4 c = *(const float4*)&P[2 * N + (size_t)i4 * 4];
    float4 d = *(const float4*)&P[3 * N + (size_t)i4 * 4];
    float4 o = make_float4(tanhf((a.x + b.x) + (c.x + d.x)),
                           tanhf((a.y + b.y) + (c.y + d.y)),
                           tanhf((a.z + b.z) + (c.z + d.z)),
                           tanhf((a.w + b.w) + (c.w + d.w)));
    *(float4*)&out[(size_t)i4 * 4] = o;
}

// ---------------------------------------------------------------------------
// Energies + masked softmax (v6: ring, staging skip, ngrp skip, f16x2 tanh)
// ---------------------------------------------------------------------------
#define EN_G(bp, accv) do { \
    float2 t = tanh2h(__hadd2(a2, (bp)[hp])); \
    accv = fmaf(v2.x, t.x, fmaf(v2.y, t.y, accv)); \
} while (0)

#define EN_HPLOOP(NG) \
    _Pragma("unroll") \
    for (int hp = 0; hp < 8; hp++) { \
        __half2 a2 = ar[hp]; \
        float2 v2 = *(const float2*)&vr[hp << 1]; \
        EN_G(b0, acc0); \
        if ((NG) > 1) EN_G(b1, acc1); \
        if ((NG) > 2) EN_G(b2, acc2); \
        if ((NG) > 3) EN_G(b3, acc3); \
    }

__global__ void __launch_bounds__(256) attn_energy_softmax(
    const int* __restrict__ lens, const float* __restrict__ v)
{
    __shared__ __align__(16) __half sBst[3][256 * 24];
    __shared__ __align__(16) __half sAh[4 * 520];
    __shared__ __align__(16) float sV[HH];
    __shared__ __align__(16) float eS[4 * 260];
    __shared__ float red[8];

    const int b  = blockIdx.y;
    const int t0 = blockIdx.x << 2;
    const int tid = threadIdx.x;
    const int t_local = tid & 3, sg = tid >> 2;
    const __half* WsQh = g_WWh;
    const __half* WhEh = g_WWh + (size_t)2048 * 512;
    const int len = lens[b];

    const int ngrp = (sg < len) ? min(4, ((len - 1 - sg) >> 6) + 1) : 0;

    {
        int row = tid >> 6, col = (tid & 63) << 3;
        uint4 x = *(const uint4*)&WsQh[((size_t)(b * TB + t0 + row)) * HH + col];
        *(uint4*)&sAh[row * 520 + col] = x;
    }
    for (int i = tid; i < HH; i += 256) sV[i] = v[i];

    const int srow0 = tid >> 1, sq = tid & 1;
    const bool st0 = srow0 < len;
    const bool st1 = srow0 + 128 < len;
    uint32_t dst0 = smem_u32(&sBst[0][srow0 * 24 + sq * 8]);
    uint32_t dst1 = smem_u32(&sBst[0][(srow0 + 128) * 24 + sq * 8]);
    const __half* src0 = WhEh + ((size_t)(b * SB) + srow0) * HH + sq * 8;
    const __half* src1 = WhEh + ((size_t)(b * SB) + srow0 + 128) * HH + sq * 8;
    const uint32_t BUFSZ = 256 * 24 * 2;

#define STAGE(hc, buf) do { \
    uint32_t o = (uint32_t)(buf) * BUFSZ; \
    if (st0) CP_ASYNC16(dst0 + o, src0 + ((hc) << 4)); \
    if (st1) CP_ASYNC16(dst1 + o, src1 + ((hc) << 4)); \
    CP_COMMIT(); \
} while (0)

    float acc0 = 0.f, acc1 = 0.f, acc2 = 0.f, acc3 = 0.f;

    STAGE(0, 0);
    STAGE(1, 1);

    int bufc = 0, bufn = 2;
    for (int hc = 0; hc < 32; hc++) {
        if (hc < 31) { CP_WAIT1(); } else { CP_WAIT0(); }
        __syncthreads();
        if (hc + 2 < 32) STAGE(hc + 2, bufn);

        const __half2* ar = (const __half2*)&sAh[t_local * 520 + (hc << 4)];
        const float*   vr = &sV[hc << 4];
        const __half2* b0 = (const __half2*)&sBst[bufc][sg * 24];
        const __half2* b1 = b0 + 64 * 12;
        const __half2* b2 = b0 + 128 * 12;
        const __half2* b3 = b0 + 192 * 12;

        switch (ngrp) {
            case 4: EN_HPLOOP(4); break;
            case 3: EN_HPLOOP(3); break;
            case 2: EN_HPLOOP(2); break;
            case 1: EN_HPLOOP(1); break;
            default: break;
        }

        bufc = (bufc + 1 == 3) ? 0 : bufc + 1;
        bufn = (bufn + 1 == 3) ? 0 : bufn + 1;
    }
#undef STAGE

    __syncthreads();
    eS[t_local * 260 + sg +   0] = acc0;
    eS[t_local * 260 + sg +  64] = acc1;
    eS[t_local * 260 + sg + 128] = acc2;
    eS[t_local * 260 + sg + 192] = acc3;
    __syncthreads();

    const int r = tid >> 6, k = tid & 63, s0 = k << 2;
    float4 ev = *(float4*)(eS + r * 260 + s0);

    float mloc = -3.0e38f;
    if (s0 + 0 < len) mloc = fmaxf(mloc, ev.x);
    if (s0 + 1 < len) mloc = fmaxf(mloc, ev.y);
    if (s0 + 2 < len) mloc = fmaxf(mloc, ev.z);
    if (s0 + 3 < len) mloc = fmaxf(mloc, ev.w);
#pragma unroll
    for (int o = 16; o; o >>= 1) mloc = fmaxf(mloc, __shfl_xor_sync(~0u, mloc, o));
    if ((tid & 31) == 0) red[tid >> 5] = mloc;
    __syncthreads();
    float m = fmaxf(red[2 * r], red[2 * r + 1]);

    float e0 = (s0 + 0 < len) ? __expf(ev.x - m) : 0.f;
    float e1 = (s0 + 1 < len) ? __expf(ev.y - m) : 0.f;
    float e2 = (s0 + 2 < len) ? __expf(ev.z - m) : 0.f;
    float e3 = (s0 + 3 < len) ? __expf(ev.w - m) : 0.f;
    float sloc = e0 + e1 + e2 + e3;
#pragma unroll
    for (int o = 16; o; o >>= 1) sloc += __shfl_xor_sync(~0u, sloc, o);
    __syncthreads();
    if ((tid & 31) == 0) red[tid >> 5] = sloc;
    __syncthreads();
    float inv = 1.f / (red[2 * r] + red[2 * r + 1]);

    float w0 = e0 * inv, w1 = e1 * inv, w2 = e2 * inv, w3 = e3 * inv;
    __nv_bfloat16 h0, l0, h1, l1, h2, l2, h3, l3;
    bfsplit(w0, h0, l0); bfsplit(w1, h1, l1);
    bfsplit(w2, h2, l2); bfsplit(w3, h3, l3);
    size_t rb = ((size_t)(b * TB + t0 + r)) * 768;
    __nv_bfloat162 hA(h0, h1), hB(h2, h3), lA(l0, l1), lB(l2, l3);
    *(__nv_bfloat162*)&g_attnS[rb + s0]           = hA;
    *(__nv_bfloat162*)&g_attnS[rb + s0 + 2]       = hB;
    *(__nv_bfloat162*)&g_attnS[rb + 256 + s0]     = lA;
    *(__nv_bfloat162*)&g_attnS[rb + 256 + s0 + 2] = lB;
    *(__nv_bfloat162*)&g_attnS[rb + 512 + s0]     = hA;
    *(__nv_bfloat162*)&g_attnS[rb + 512 + s0 + 2] = hB;
}

// ---------------------------------------------------------------------------

extern "C" void kernel_launch(void* const* d_in, const int* in_sizes, int n_in,
                              void* d_out, int out_size)
{
    (void)in_sizes; (void)n_in; (void)out_size;
    const float* query = (const float*)d_in[0];
    const float* enc   = (const float*)d_in[1];
    const int*   lens  = (const int*)d_in[2];
    const float* W_s   = (const float*)d_in[3];
    const float* W_h   = (const float*)d_in[4];
    const float* v     = (const float*)d_in[5];
    const float* W_out = (const float*)d_in[6];
    float* out = (float*)d_out;

    __nv_bfloat16 *pin3, *pW12, *pWo3, *pA5, *pAttnS, *peT;
    __half* pWWh;
    float* pP5;
    cudaGetSymbolAddress((void**)&pin3, g_in3);
    cudaGetSymbolAddress((void**)&pW12, g_W12);
    cudaGetSymbolAddress((void**)&pWo3, g_Wo3);
    cudaGetSymbolAddress((void**)&pWWh, g_WWh);
    cudaGetSymbolAddress((void**)&pA5, g_A5);
    cudaGetSymbolAddress((void**)&pAttnS, g_attnS);
    cudaGetSymbolAddress((void**)&peT, g_eT);
    cudaGetSymbolAddress((void**)&pP5, g_P5);

    conv_inputs<<<2048, 256>>>(query, enc);
    conv_weights<<<1024, 256>>>(W_s, W_h, W_out);
    transpose_split_enc<<<dim3(16, 8, 8), 256>>>(enc, peT);

    // 1+2) WsQ / WhE batched (z=2), 2-term split K'=1024, half epilogue
    hmma_gemm<3, 128><<<dim3(4, 16, 2), 256>>>(pin3, pW12, pWWh, 1024, 1024, 512,
                                               (size_t)2048 * 1024, (size_t)512 * 1024,
                                               (size_t)2048 * 512, lens);
    // 3) energies + masked softmax
    attn_energy_softmax<<<dim3(64, 8), 256>>>(lens, v);
    // 4) context = attn @ enc -> A5 ctx half (3-term, K'=768)
    hmma_gemm<2, 64><<<dim3(8, 2, 8), 256>>>(pAttnS, peT, pA5, 768, 768, 3072,
                                             (size_t)TB * 768, (size_t)HH * 768,
                                             (size_t)TB * 3072, nullptr);
    // 5) out GEMM split-K x4 in ONE launch (z=4, K segs of 768) + reduce
    hmma_gemm<0, 128><<<dim3(4, 16, 4), 256>>>(pA5, pWo3, pP5, 768, 3072, 512,
                                               (size_t)768, (size_t)768,
                                               (size_t)2048 * 512, nullptr);
    reduce4_tanh<<<1024, 256>>>(pP5, out);
}

// round 17
// speedup vs baseline: 1.1053x; 1.0265x over previous
#include <cuda_runtime.h>
#include <cuda_bf16.h>
#include <cuda_fp16.h>
#include <cstdint>
#include <math.h>

#define BB 8
#define TB 256
#define SB 256
#define HH 512

// ---------------------------------------------------------------------------
// Static device scratch
// ---------------------------------------------------------------------------
__device__ __nv_bfloat16 g_in3[2 * 2048 * 1536];  // query|enc 2-term A splits (K'=1024)
__device__ __nv_bfloat16 g_W12[2 * 512 * 1536];   // W_s|W_h 2-term B splits (K'=1024)
__device__ __nv_bfloat16 g_Wo3[512 * 3072];       // W_out 3-term B split
__device__ __half g_WWh[2 * 2048 * 512];          // WsQ | WhE  (half)
__device__ __nv_bfloat16 g_A5[2048 * 3072];       // [ctx|query] 3-term split (A-form)
__device__ __nv_bfloat16 g_attnS[BB * TB * 768];  // attn 3-term split (A-form)
__device__ __nv_bfloat16 g_eT[BB * HH * 768];     // enc^T 3-term split (B-form)
__device__ float g_P5[4 * 2048 * 512];            // split-K x4 partials for out GEMM

typedef unsigned long long u64;

__device__ __forceinline__ uint32_t smem_u32(const void* p) {
    uint32_t a;
    asm("{ .reg .u64 t; cvta.to.shared.u64 t, %1; cvt.u32.u64 %0, t; }" : "=r"(a) : "l"(p));
    return a;
}
__device__ __forceinline__ void bfsplit(float x, __nv_bfloat16& h, __nv_bfloat16& l) {
    h = __float2bfloat16(x);
    l = __float2bfloat16(x - __bfloat162float(h));
}
__device__ __forceinline__ float2 tanh2h(__half2 x) {
    uint32_t u = *reinterpret_cast<uint32_t*>(&x);
    asm("tanh.approx.f16x2 %0, %0;" : "+r"(u));
    __half2 t = *reinterpret_cast<__half2*>(&u);
    return __half22float2(t);
}

#define CP_ASYNC16(dst, src) \
    asm volatile("cp.async.cg.shared.global [%0], [%1], 16;" :: "r"(dst), "l"(src))
#define CP_COMMIT() asm volatile("cp.async.commit_group;" ::: "memory")
#define CP_WAIT2()  asm volatile("cp.async.wait_group 2;" ::: "memory")
#define CP_WAIT1()  asm volatile("cp.async.wait_group 1;" ::: "memory")
#define CP_WAIT0()  asm volatile("cp.async.wait_group 0;" ::: "memory")

// ---------------------------------------------------------------------------
// Fused conversions (R14 layouts)
// ---------------------------------------------------------------------------
__global__ void __launch_bounds__(256) conv_inputs(
    const float* __restrict__ q, const float* __restrict__ enc)
{
    int t = blockIdx.x * 256 + threadIdx.x;
    const int perT = 2048 * 512 / 4;
    bool isQ = t < perT;
    int i4 = isQ ? t : t - perT;
    int r = i4 >> 7, k = (i4 & 127) << 2;
    const float* src = isQ ? q : enc;
    float4 x = *(const float4*)&src[(size_t)r * 512 + k];
    __nv_bfloat16 h0, l0, h1, l1, h2, l2, h3, l3;
    bfsplit(x.x, h0, l0); bfsplit(x.y, h1, l1);
    bfsplit(x.z, h2, l2); bfsplit(x.w, h3, l3);
    __nv_bfloat162 hA(h0, h1), hB(h2, h3), lA(l0, l1), lB(l2, l3);

    size_t base = (isQ ? 0 : (size_t)2048 * 1024) + (size_t)r * 1024 + k;
    *(__nv_bfloat162*)&g_in3[base]           = hA;
    *(__nv_bfloat162*)&g_in3[base + 2]       = hB;
    *(__nv_bfloat162*)&g_in3[base + 512]     = lA;
    *(__nv_bfloat162*)&g_in3[base + 512 + 2] = lB;

    if (isQ) {
        size_t b5 = (size_t)r * 3072 + 512 + k;
        *(__nv_bfloat162*)&g_A5[b5]            = hA;
        *(__nv_bfloat162*)&g_A5[b5 + 2]        = hB;
        *(__nv_bfloat162*)&g_A5[b5 + 1024]     = lA;
        *(__nv_bfloat162*)&g_A5[b5 + 1024 + 2] = lB;
        *(__nv_bfloat162*)&g_A5[b5 + 2048]     = hA;
        *(__nv_bfloat162*)&g_A5[b5 + 2048 + 2] = hB;
    }
}

__global__ void __launch_bounds__(256) conv_weights(
    const float* __restrict__ Ws, const float* __restrict__ Wh,
    const float* __restrict__ Wo)
{
    int t = blockIdx.x * 256 + threadIdx.x;
    if (t < 131072) {
        const float* src; __nv_bfloat16* dst; int i4;
        if (t < 65536) { src = Ws; dst = g_W12;              i4 = t; }
        else           { src = Wh; dst = g_W12 + 512 * 1024; i4 = t - 65536; }
        int r = i4 >> 7, k = (i4 & 127) << 2;
        float4 x = *(const float4*)&src[(size_t)r * 512 + k];
        __nv_bfloat162 hA(__float2bfloat16(x.x), __float2bfloat16(x.y));
        __nv_bfloat162 hB(__float2bfloat16(x.z), __float2bfloat16(x.w));
        size_t base = (size_t)r * 1024 + k;
        *(__nv_bfloat162*)&dst[base]           = hA;
        *(__nv_bfloat162*)&dst[base + 2]       = hB;
        *(__nv_bfloat162*)&dst[base + 512]     = hA;
        *(__nv_bfloat162*)&dst[base + 512 + 2] = hB;
    } else {
        int i4 = t - 131072;
        int r = i4 >> 8, k = (i4 & 255) << 2;
        float4 x = *(const float4*)&Wo[(size_t)r * 1024 + k];
        __nv_bfloat16 h0, l0, h1, l1, h2, l2, h3, l3;
        bfsplit(x.x, h0, l0); bfsplit(x.y, h1, l1);
        bfsplit(x.z, h2, l2); bfsplit(x.w, h3, l3);
        __nv_bfloat162 hA(h0, h1), hB(h2, h3), lA(l0, l1), lB(l2, l3);
        size_t base = (size_t)r * 3072 + k;
        *(__nv_bfloat162*)&g_Wo3[base]            = hA;
        *(__nv_bfloat162*)&g_Wo3[base + 2]        = hB;
        *(__nv_bfloat162*)&g_Wo3[base + 1024]     = hA;
        *(__nv_bfloat162*)&g_Wo3[base + 1024 + 2] = hB;
        *(__nv_bfloat162*)&g_Wo3[base + 2048]     = lA;
        *(__nv_bfloat162*)&g_Wo3[base + 2048 + 2] = lB;
    }
}

__global__ void __launch_bounds__(256) transpose_split_enc(
    const float* __restrict__ enc, __nv_bfloat16* __restrict__ eT)
{
    __shared__ float tile[32][33];
    const int h0 = blockIdx.x * 32, s0 = blockIdx.y * 32, b = blockIdx.z;
    const int tx = threadIdx.x & 31, ty = threadIdx.x >> 5;
    const float* ep = enc + ((size_t)b * SB + s0) * HH + h0;
#pragma unroll
    for (int i = 0; i < 4; i++)
        tile[ty + 8 * i][tx] = ep[(size_t)(ty + 8 * i) * HH + tx];
    __syncthreads();
#pragma unroll
    for (int i = 0; i < 4; i++) {
        int hl = ty + 8 * i, sl = tx;
        __nv_bfloat16 h, l; bfsplit(tile[sl][hl], h, l);
        size_t base = ((size_t)b * HH + h0 + hl) * 768 + s0 + sl;
        eT[base] = h; eT[base + 256] = h; eT[base + 512] = l;
    }
}

// ---------------------------------------------------------------------------
// HMMA GEMM, 3-stage cp.async ring. R11-style mainloop (no reg double-buffer)
// + __launch_bounds__(256, 2): <=128 regs -> 2 CTAs/SM.
// EPI: 0 fp32 | 1 tanh fp32 | 2 hi/lo/hi bf16 split (A5) | 3 half store
// ---------------------------------------------------------------------------
__device__ __forceinline__ void mma16816(float* c, const uint32_t* a, const uint32_t* b) {
    asm volatile(
        "mma.sync.aligned.m16n8k16.row.col.f32.bf16.bf16.f32 "
        "{%0,%1,%2,%3}, {%4,%5,%6,%7}, {%8,%9}, {%0,%1,%2,%3};"
        : "+f"(c[0]), "+f"(c[1]), "+f"(c[2]), "+f"(c[3])
        : "r"(a[0]), "r"(a[1]), "r"(a[2]), "r"(a[3]), "r"(b[0]), "r"(b[1]));
}

template <int EPI, int NT>
__global__ void __launch_bounds__(256, 2) hmma_gemm(
    const __nv_bfloat16* __restrict__ A, const __nv_bfloat16* __restrict__ B,
    void* Cv, int K_len, int Kld, int ldc, size_t strA, size_t strB, size_t strC,
    const int* __restrict__ lens)
{
    constexpr int NPG = NT / 32;
    constexpr int NTT = NT / 16;
    constexpr uint32_t ASZ = 128 * 40 * 2;
    constexpr uint32_t BSZ = NT * 40 * 2;

    __shared__ __align__(16) __nv_bfloat16 As[3][128][40];
    __shared__ __align__(16) __nv_bfloat16 Bs[3][NT][40];

    const int row0 = blockIdx.y * 128, col0 = blockIdx.x * NT;
    if (lens != nullptr && blockIdx.z == 1) {
        if ((row0 & 255) >= lens[row0 >> 8]) return;
    }

    A += (size_t)blockIdx.z * strA;
    B += (size_t)blockIdx.z * strB;

    const int tid = threadIdx.x, wid = tid >> 5, lane = tid & 31;
    const int wm = wid & 3, wn = wid >> 2;

    float acc[2][NTT][4];
#pragma unroll
    for (int mt = 0; mt < 2; mt++)
#pragma unroll
        for (int nt = 0; nt < NTT; nt++)
#pragma unroll
            for (int i = 0; i < 4; i++) acc[mt][nt][i] = 0.f;

    uint32_t a_addr[2], b_addr[NPG];
#pragma unroll
    for (int mt = 0; mt < 2; mt++) {
        int r = wm * 32 + mt * 16 + (lane & 7) + ((lane >> 3) & 1) * 8;
        int k = (lane >> 4) * 8;
        a_addr[mt] = smem_u32(&As[0][r][k]);
    }
#pragma unroll
    for (int np = 0; np < NPG; np++) {
        int n = wn * (NT / 2) + np * 16 + (lane & 7) + (lane >> 4) * 8;
        int k = ((lane >> 3) & 1) * 8;
        b_addr[np] = smem_u32(&Bs[0][n][k]);
    }

    const int arow = tid >> 2, acol = (tid & 3) * 8;
    uint32_t sA0 = smem_u32(&As[0][arow][acol]);
    uint32_t sA1 = smem_u32(&As[0][64 + arow][acol]);
    uint32_t sB0 = smem_u32(&Bs[0][arow][acol]);
    uint32_t sB1 = (NT == 128) ? smem_u32(&Bs[0][(NT == 128 ? 64 : 0) + arow][acol]) : 0;
    const __nv_bfloat16* gA0 = A + (size_t)(row0 + arow) * Kld + acol;
    const __nv_bfloat16* gA1 = A + (size_t)(row0 + 64 + arow) * Kld + acol;
    const __nv_bfloat16* gB0 = B + (size_t)(col0 + arow) * Kld + acol;
    const __nv_bfloat16* gB1 = (NT == 128)
        ? B + (size_t)(col0 + 64 + arow) * Kld + acol : gB0;

#define ISSUE(kc, st) do { \
    uint32_t ao = (uint32_t)(st) * ASZ, bo = (uint32_t)(st) * BSZ; \
    CP_ASYNC16(sA0 + ao, gA0 + (kc)); \
    CP_ASYNC16(sA1 + ao, gA1 + (kc)); \
    CP_ASYNC16(sB0 + bo, gB0 + (kc)); \
    if (NT == 128) CP_ASYNC16(sB1 + bo, gB1 + (kc)); \
    CP_COMMIT(); \
} while (0)

    const int nch = K_len >> 5;
    ISSUE(0, 0);
    if (nch > 1) ISSUE(32, 1);

    int stage = 0;
    for (int i = 0; i < nch; i++) {
        if (i + 2 < nch) {
            int s2 = stage + 2; if (s2 >= 3) s2 -= 3;
            ISSUE((i + 2) << 5, s2);
            CP_WAIT2();
        } else if (i + 1 < nch) {
            CP_WAIT1();
        } else {
            CP_WAIT0();
        }
        __syncthreads();

        const uint32_t aoff = (uint32_t)stage * ASZ, boff = (uint32_t)stage * BSZ;
#pragma unroll
        for (int ks = 0; ks < 2; ks++) {
            uint32_t a[2][4], b[NTT][2];
#pragma unroll
            for (int mt = 0; mt < 2; mt++) {
                asm volatile("ldmatrix.sync.aligned.m8n8.x4.shared.b16 {%0,%1,%2,%3}, [%4];"
                    : "=r"(a[mt][0]), "=r"(a[mt][1]), "=r"(a[mt][2]), "=r"(a[mt][3])
                    : "r"(a_addr[mt] + aoff + ks * 32));
            }
#pragma unroll
            for (int np = 0; np < NPG; np++) {
                asm volatile("ldmatrix.sync.aligned.m8n8.x4.shared.b16 {%0,%1,%2,%3}, [%4];"
                    : "=r"(b[np * 2][0]), "=r"(b[np * 2][1]),
                      "=r"(b[np * 2 + 1][0]), "=r"(b[np * 2 + 1][1])
                    : "r"(b_addr[np] + boff + ks * 32));
            }
#pragma unroll
            for (int mt = 0; mt < 2; mt++)
#pragma unroll
                for (int nt = 0; nt < NTT; nt++)
                    mma16816(acc[mt][nt], a[mt], b[nt]);
        }
        __syncthreads();
        if (++stage == 3) stage = 0;
    }
#undef ISSUE

    if (EPI == 2) {
        __nv_bfloat16* Cb = (__nv_bfloat16*)Cv + (size_t)blockIdx.z * strC;
#pragma unroll
        for (int mt = 0; mt < 2; mt++)
#pragma unroll
            for (int nt = 0; nt < NTT; nt++) {
                int m = row0 + wm * 32 + mt * 16 + (lane >> 2);
                int n = col0 + wn * (NT / 2) + nt * 8 + 2 * (lane & 3);
#pragma unroll
                for (int rr = 0; rr < 2; rr++) {
                    int mr = m + rr * 8;
                    float v0 = acc[mt][nt][rr * 2], v1 = acc[mt][nt][rr * 2 + 1];
                    __nv_bfloat16 h0, l0, h1, l1;
                    bfsplit(v0, h0, l0); bfsplit(v1, h1, l1);
                    size_t base = (size_t)mr * ldc + n;
                    *(__nv_bfloat162*)&Cb[base]        = __nv_bfloat162(h0, h1);
                    *(__nv_bfloat162*)&Cb[base + 1024] = __nv_bfloat162(l0, l1);
                    *(__nv_bfloat162*)&Cb[base + 2048] = __nv_bfloat162(h0, h1);
                }
            }
    } else if (EPI == 3) {
        __half* Ch = (__half*)Cv + (size_t)blockIdx.z * strC;
#pragma unroll
        for (int mt = 0; mt < 2; mt++)
#pragma unroll
            for (int nt = 0; nt < NTT; nt++) {
                int m = row0 + wm * 32 + mt * 16 + (lane >> 2);
                int n = col0 + wn * (NT / 2) + nt * 8 + 2 * (lane & 3);
                *(__half2*)&Ch[(size_t)m * ldc + n] =
                    __floats2half2_rn(acc[mt][nt][0], acc[mt][nt][1]);
                *(__half2*)&Ch[(size_t)(m + 8) * ldc + n] =
                    __floats2half2_rn(acc[mt][nt][2], acc[mt][nt][3]);
            }
    } else {
        float* Cf = (float*)Cv + (size_t)blockIdx.z * strC;
#pragma unroll
        for (int mt = 0; mt < 2; mt++)
#pragma unroll
            for (int nt = 0; nt < NTT; nt++) {
                int m = row0 + wm * 32 + mt * 16 + (lane >> 2);
                int n = col0 + wn * (NT / 2) + nt * 8 + 2 * (lane & 3);
                float c0 = acc[mt][nt][0], c1 = acc[mt][nt][1];
                float c2 = acc[mt][nt][2], c3 = acc[mt][nt][3];
                if (EPI == 1) { c0 = tanhf(c0); c1 = tanhf(c1); c2 = tanhf(c2); c3 = tanhf(c3); }
                *(float2*)&Cf[(size_t)m * ldc + n] = make_float2(c0, c1);
                *(float2*)&Cf[(size_t)(m + 8) * ldc + n] = make_float2(c2, c3);
            }
    }
}

// 4-way split-K reduction + tanh
__global__ void __launch_bounds__(256) reduce4_tanh(
    const float* __restrict__ P, float* __restrict__ out)
{
    const size_t N = (size_t)2048 * 512;
    int i4 = blockIdx.x * 256 + threadIdx.x;
    float4 a = *(const float4*)&P[(size_t)i4 * 4];
    float4 b = *(const float4*)&P[N + (size_t)i4 * 4];
    float4 c = *(const float4*)&P[2 * N + (size_t)i4 * 4];
    float4 d = *(const float4*)&P[3 * N + (size_t)i4 * 4];
    float4 o = make_float4(tanhf((a.x + b.x) + (c.x + d.x)),
                           tanhf((a.y + b.y) + (c.y + d.y)),
                           tanhf((a.z + b.z) + (c.z + d.z)),
                           tanhf((a.w + b.w) + (c.w + d.w)));
    *(float4*)&out[(size_t)i4 * 4] = o;
}

// ---------------------------------------------------------------------------
// Energies + masked softmax (v6: ring, staging skip, ngrp skip, f16x2 tanh)
// ---------------------------------------------------------------------------
#define EN_G(bp, accv) do { \
    float2 t = tanh2h(__hadd2(a2, (bp)[hp])); \
    accv = fmaf(v2.x, t.x, fmaf(v2.y, t.y, accv)); \
} while (0)

#define EN_HPLOOP(NG) \
    _Pragma("unroll") \
    for (int hp = 0; hp < 8; hp++) { \
        __half2 a2 = ar[hp]; \
        float2 v2 = *(const float2*)&vr[hp << 1]; \
        EN_G(b0, acc0); \
        if ((NG) > 1) EN_G(b1, acc1); \
        if ((NG) > 2) EN_G(b2, acc2); \
        if ((NG) > 3) EN_G(b3, acc3); \
    }

__global__ void __launch_bounds__(256) attn_energy_softmax(
    const int* __restrict__ lens, const float* __restrict__ v)
{
    __shared__ __align__(16) __half sBst[3][256 * 24];
    __shared__ __align__(16) __half sAh[4 * 520];
    __shared__ __align__(16) float sV[HH];
    __shared__ __align__(16) float eS[4 * 260];
    __shared__ float red[8];

    const int b  = blockIdx.y;
    const int t0 = blockIdx.x << 2;
    const int tid = threadIdx.x;
    const int t_local = tid & 3, sg = tid >> 2;
    const __half* WsQh = g_WWh;
    const __half* WhEh = g_WWh + (size_t)2048 * 512;
    const int len = lens[b];

    const int ngrp = (sg < len) ? min(4, ((len - 1 - sg) >> 6) + 1) : 0;

    {
        int row = tid >> 6, col = (tid & 63) << 3;
        uint4 x = *(const uint4*)&WsQh[((size_t)(b * TB + t0 + row)) * HH + col];
        *(uint4*)&sAh[row * 520 + col] = x;
    }
    for (int i = tid; i < HH; i += 256) sV[i] = v[i];

    const int srow0 = tid >> 1, sq = tid & 1;
    const bool st0 = srow0 < len;
    const bool st1 = srow0 + 128 < len;
    uint32_t dst0 = smem_u32(&sBst[0][srow0 * 24 + sq * 8]);
    uint32_t dst1 = smem_u32(&sBst[0][(srow0 + 128) * 24 + sq * 8]);
    const __half* src0 = WhEh + ((size_t)(b * SB) + srow0) * HH + sq * 8;
    const __half* src1 = WhEh + ((size_t)(b * SB) + srow0 + 128) * HH + sq * 8;
    const uint32_t BUFSZ = 256 * 24 * 2;

#define STAGE(hc, buf) do { \
    uint32_t o = (uint32_t)(buf) * BUFSZ; \
    if (st0) CP_ASYNC16(dst0 + o, src0 + ((hc) << 4)); \
    if (st1) CP_ASYNC16(dst1 + o, src1 + ((hc) << 4)); \
    CP_COMMIT(); \
} while (0)

    float acc0 = 0.f, acc1 = 0.f, acc2 = 0.f, acc3 = 0.f;

    STAGE(0, 0);
    STAGE(1, 1);

    int bufc = 0, bufn = 2;
    for (int hc = 0; hc < 32; hc++) {
        if (hc < 31) { CP_WAIT1(); } else { CP_WAIT0(); }
        __syncthreads();
        if (hc + 2 < 32) STAGE(hc + 2, bufn);

        const __half2* ar = (const __half2*)&sAh[t_local * 520 + (hc << 4)];
        const float*   vr = &sV[hc << 4];
        const __half2* b0 = (const __half2*)&sBst[bufc][sg * 24];
        const __half2* b1 = b0 + 64 * 12;
        const __half2* b2 = b0 + 128 * 12;
        const __half2* b3 = b0 + 192 * 12;

        switch (ngrp) {
            case 4: EN_HPLOOP(4); break;
            case 3: EN_HPLOOP(3); break;
            case 2: EN_HPLOOP(2); break;
            case 1: EN_HPLOOP(1); break;
            default: break;
        }

        bufc = (bufc + 1 == 3) ? 0 : bufc + 1;
        bufn = (bufn + 1 == 3) ? 0 : bufn + 1;
    }
#undef STAGE

    __syncthreads();
    eS[t_local * 260 + sg +   0] = acc0;
    eS[t_local * 260 + sg +  64] = acc1;
    eS[t_local * 260 + sg + 128] = acc2;
    eS[t_local * 260 + sg + 192] = acc3;
    __syncthreads();

    const int r = tid >> 6, k = tid & 63, s0 = k << 2;
    float4 ev = *(float4*)(eS + r * 260 + s0);

    float mloc = -3.0e38f;
    if (s0 + 0 < len) mloc = fmaxf(mloc, ev.x);
    if (s0 + 1 < len) mloc = fmaxf(mloc, ev.y);
    if (s0 + 2 < len) mloc = fmaxf(mloc, ev.z);
    if (s0 + 3 < len) mloc = fmaxf(mloc, ev.w);
#pragma unroll
    for (int o = 16; o; o >>= 1) mloc = fmaxf(mloc, __shfl_xor_sync(~0u, mloc, o));
    if ((tid & 31) == 0) red[tid >> 5] = mloc;
    __syncthreads();
    float m = fmaxf(red[2 * r], red[2 * r + 1]);

    float e0 = (s0 + 0 < len) ? __expf(ev.x - m) : 0.f;
    float e1 = (s0 + 1 < len) ? __expf(ev.y - m) : 0.f;
    float e2 = (s0 + 2 < len) ? __expf(ev.z - m) : 0.f;
    float e3 = (s0 + 3 < len) ? __expf(ev.w - m) : 0.f;
    float sloc = e0 + e1 + e2 + e3;
#pragma unroll
    for (int o = 16; o; o >>= 1) sloc += __shfl_xor_sync(~0u, sloc, o);
    __syncthreads();
    if ((tid & 31) == 0) red[tid >> 5] = sloc;
    __syncthreads();
    float inv = 1.f / (red[2 * r] + red[2 * r + 1]);

    float w0 = e0 * inv, w1 = e1 * inv, w2 = e2 * inv, w3 = e3 * inv;
    __nv_bfloat16 h0, l0, h1, l1, h2, l2, h3, l3;
    bfsplit(w0, h0, l0); bfsplit(w1, h1, l1);
    bfsplit(w2, h2, l2); bfsplit(w3, h3, l3);
    size_t rb = ((size_t)(b * TB + t0 + r)) * 768;
    __nv_bfloat162 hA(h0, h1), hB(h2, h3), lA(l0, l1), lB(l2, l3);
    *(__nv_bfloat162*)&g_attnS[rb + s0]           = hA;
    *(__nv_bfloat162*)&g_attnS[rb + s0 + 2]       = hB;
    *(__nv_bfloat162*)&g_attnS[rb + 256 + s0]     = lA;
    *(__nv_bfloat162*)&g_attnS[rb + 256 + s0 + 2] = lB;
    *(__nv_bfloat162*)&g_attnS[rb + 512 + s0]     = hA;
    *(__nv_bfloat162*)&g_attnS[rb + 512 + s0 + 2] = hB;
}

// ---------------------------------------------------------------------------

extern "C" void kernel_launch(void* const* d_in, const int* in_sizes, int n_in,
                              void* d_out, int out_size)
{
    (void)in_sizes; (void)n_in; (void)out_size;
    const float* query = (const float*)d_in[0];
    const float* enc   = (const float*)d_in[1];
    const int*   lens  = (const int*)d_in[2];
    const float* W_s   = (const float*)d_in[3];
    const float* W_h   = (const float*)d_in[4];
    const float* v     = (const float*)d_in[5];
    const float* W_out = (const float*)d_in[6];
    float* out = (float*)d_out;

    __nv_bfloat16 *pin3, *pW12, *pWo3, *pA5, *pAttnS, *peT;
    __half* pWWh;
    float* pP5;
    cudaGetSymbolAddress((void**)&pin3, g_in3);
    cudaGetSymbolAddress((void**)&pW12, g_W12);
    cudaGetSymbolAddress((void**)&pWo3, g_Wo3);
    cudaGetSymbolAddress((void**)&pWWh, g_WWh);
    cudaGetSymbolAddress((void**)&pA5, g_A5);
    cudaGetSymbolAddress((void**)&pAttnS, g_attnS);
    cudaGetSymbolAddress((void**)&peT, g_eT);
    cudaGetSymbolAddress((void**)&pP5, g_P5);

    conv_inputs<<<2048, 256>>>(query, enc);
    conv_weights<<<1024, 256>>>(W_s, W_h, W_out);
    transpose_split_enc<<<dim3(16, 8, 8), 256>>>(enc, peT);

    // 1+2) WsQ / WhE batched (z=2), 2-term split K'=1024, half epilogue
    hmma_gemm<3, 128><<<dim3(4, 16, 2), 256>>>(pin3, pW12, pWWh, 1024, 1024, 512,
                                               (size_t)2048 * 1024, (size_t)512 * 1024,
                                               (size_t)2048 * 512, lens);
    // 3) energies + masked softmax
    attn_energy_softmax<<<dim3(64, 8), 256>>>(lens, v);
    // 4) context = attn @ enc -> A5 ctx half (3-term, K'=768)
    hmma_gemm<2, 64><<<dim3(8, 2, 8), 256>>>(pAttnS, peT, pA5, 768, 768, 3072,
                                             (size_t)TB * 768, (size_t)HH * 768,
                                             (size_t)TB * 3072, nullptr);
    // 5) out GEMM split-K x4 in ONE launch (z=4, K segs of 768) + reduce
    hmma_gemm<0, 128><<<dim3(4, 16, 4), 256>>>(pA5, pWo3, pP5, 768, 3072, 512,
                                               (size_t)768, (size_t)768,
                                               (size_t)2048 * 512, nullptr);
    reduce4_tanh<<<1024, 256>>>(pP5, out);
}